// round 6
// baseline (speedup 1.0000x reference)
#include <cuda_runtime.h>
#include <math.h>

#define NN 50000
#define EE 800000
#define D 96
#define HID 32
#define HEADS 3
#define FIN 16
#define F0 8
#define EDIM 4

// ---- scratch (static device globals; zero-initialized at module load) ----
__device__ float g_h0[NN * F0];
__device__ float g_h1[NN * D];
__device__ float g_Q[NN * D];
__device__ float g_K[NN * D];
__device__ float g_V[NN * D];
__device__ float g_S[NN * D];
__device__ int   g_cnt[NN];          // must be zero at entry of every launch (self-restoring)
__device__ int   g_rowptr[NN + 1];
__device__ int   g_cur[NN];
__device__ int   g_psrc[EE];         // src index in CSR-permuted order
__device__ float4 g_pea[EE];         // edge_attr in CSR-permuted order
// decoupled-lookback scan state (zeroed each launch by kernel 0)
__device__ volatile int g_lb_status[64];  // 0=invalid 1=aggregate 2=prefix
__device__ volatile int g_lb_agg[64];
__device__ volatile int g_lb_pref[64];

// ------- launch 0: layer-0 MLP + dst histogram + lookback-state zeroing -------
__global__ void k_l0_hist(const float* __restrict__ x, const float* __restrict__ W1,
                          const float* __restrict__ b1, const int* __restrict__ dst,
                          int n, int e) {
    int i = blockIdx.x * blockDim.x + threadIdx.x;
    if (i < 64) g_lb_status[i] = 0;
    if (i < e) atomicAdd(&g_cnt[dst[i]], 1);
    if (i >= n) return;
    float xr[FIN];
    const float4* xv = reinterpret_cast<const float4*>(x + i * FIN);
#pragma unroll
    for (int j = 0; j < 4; j++) {
        float4 t = xv[j];
        xr[j * 4 + 0] = t.x; xr[j * 4 + 1] = t.y; xr[j * 4 + 2] = t.z; xr[j * 4 + 3] = t.w;
    }
#pragma unroll
    for (int o = 0; o < F0; o++) {
        float acc = b1[o];
#pragma unroll
        for (int k = 0; k < FIN; k++) acc += xr[k] * W1[k * F0 + o];
        g_h0[i * F0 + o] = tanhf(acc);
    }
}

// ------- launch 1: single-pass scan (decoupled lookback); zeroes g_cnt after use -------
__global__ void k_scan_lb(int n, int etot) {
    __shared__ int sh[256];
    __shared__ int sh_off;
    int b = blockIdx.x, t = threadIdx.x;
    int base = (b * 256 + t) * 4;
    int c[4];
    int local = 0;
#pragma unroll
    for (int j = 0; j < 4; j++) {
        int i = base + j;
        c[j] = (i < n) ? g_cnt[i] : 0;
        if (i < n) g_cnt[i] = 0;     // self-restore for next launch
        local += c[j];
    }
    sh[t] = local;
    __syncthreads();
    for (int off = 1; off < 256; off <<= 1) {
        int u = (t >= off) ? sh[t - off] : 0;
        __syncthreads();
        sh[t] += u;
        __syncthreads();
    }
    int incl = sh[t];
    int agg = sh[255];
    if (t == 255) {
        g_lb_agg[b] = agg;
        __threadfence();
        g_lb_status[b] = (b == 0) ? 0 : 1;
    }
    __syncthreads();
    if (t == 0) {
        int excl = 0;
        for (int p = b - 1; p >= 0; --p) {
            int st;
            do { st = g_lb_status[p]; } while (st == 0);
            if (st == 2) { excl += g_lb_pref[p]; break; }
            excl += g_lb_agg[p];
        }
        sh_off = excl;
        g_lb_pref[b] = excl + agg;
        __threadfence();
        g_lb_status[b] = 2;
        if (b == 0) g_rowptr[n] = etot;
    }
    __syncthreads();
    int run = sh_off + incl - local;
#pragma unroll
    for (int j = 0; j < 4; j++) {
        int i = base + j;
        if (i < n) {
            g_rowptr[i] = run;
            g_cur[i] = run;
            run += c[j];
        }
    }
}

// ------- proj body: 256 threads, 2 groups of 96 compute threads, 8 nodes each -------
// Q,K,V,S = in @ {Wq,Wk,Wv,Ws} + bias. 1 shared load feeds 4 FMAs.
template <int FI>
__device__ __forceinline__ void proj_body(
        const float* __restrict__ in, int node0,
        const float* __restrict__ Wq, const float* __restrict__ bq,
        const float* __restrict__ Wk, const float* __restrict__ bk,
        const float* __restrict__ Wv, const float* __restrict__ bv,
        const float* __restrict__ Ws, const float* __restrict__ bs,
        int n, float* shp) {
    const int NB = 16, NG = 8;          // nodes per block / per group
    float (*sh)[FI] = (float (*)[FI])shp;
    int t = threadIdx.x;
    for (int idx = t; idx < NB * FI; idx += 256) {
        int j = idx / FI, k = idx % FI;
        int nd = node0 + j;
        sh[j][k] = (nd < n) ? in[nd * FI + k] : 0.0f;
    }
    __syncthreads();
    int grp = t / D;                    // 0,1 compute; 2 idle (t>=192)
    int d = t - grp * D;
    if (grp < 2) {
        int j0 = grp * NG;
        float aq[NG], ak[NG], av[NG], as_[NG];
        float vbq = bq[d], vbk = bk[d], vbv = bv[d], vbs = bs[d];
#pragma unroll
        for (int j = 0; j < NG; j++) { aq[j] = vbq; ak[j] = vbk; av[j] = vbv; as_[j] = vbs; }
        for (int k = 0; k < FI; k++) {
            float wq = Wq[k * D + d], wk = Wk[k * D + d], wv = Wv[k * D + d], ws = Ws[k * D + d];
#pragma unroll
            for (int j = 0; j < NG; j++) {
                float h = sh[j0 + j][k];
                aq[j] += h * wq; ak[j] += h * wk; av[j] += h * wv; as_[j] += h * ws;
            }
        }
#pragma unroll
        for (int j = 0; j < NG; j++) {
            int nd = node0 + j0 + j;
            if (nd < n) {
                g_Q[nd * D + d] = aq[j];
                g_K[nd * D + d] = ak[j];
                g_V[nd * D + d] = av[j];
                g_S[nd * D + d] = as_[j];
            }
        }
    }
}

// ------- launch 2: fused scatter (blocks [0,SB)) + layer-1 projection (rest) -------
__global__ void k_scatter_proj1(const int* __restrict__ src, const int* __restrict__ dst,
                                const float4* __restrict__ ea, int e, int scat_blocks,
                                const float* __restrict__ Wq, const float* __restrict__ bq,
                                const float* __restrict__ Wk, const float* __restrict__ bk,
                                const float* __restrict__ Wv, const float* __restrict__ bv,
                                const float* __restrict__ Ws, const float* __restrict__ bs,
                                int n) {
    __shared__ float shp[16 * F0];
    if ((int)blockIdx.x < scat_blocks) {
        int i = blockIdx.x * 256 + threadIdx.x;
        if (i < e) {
            int d = dst[i];
            int pos = atomicAdd(&g_cur[d], 1);
            g_psrc[pos] = src[i];
            g_pea[pos] = ea[i];
        }
    } else {
        int node0 = (blockIdx.x - scat_blocks) * 16;
        proj_body<F0>(g_h0, node0, Wq, bq, Wk, bk, Wv, bv, Ws, bs, n, shp);
    }
}

// ------- launch 4: layer-2 projection -------
__global__ void k_proj2(const float* __restrict__ Wq, const float* __restrict__ bq,
                        const float* __restrict__ Wk, const float* __restrict__ bk,
                        const float* __restrict__ Wv, const float* __restrict__ bv,
                        const float* __restrict__ Ws, const float* __restrict__ bs,
                        int n) {
    __shared__ float shp[16 * D];
    int node0 = blockIdx.x * 16;
    proj_body<D>(g_h1, node0, Wq, bq, Wk, bk, Wv, bv, Ws, bs, n, shp);
}

// ------- attention: warp per destination node, online softmax, 2-stage pipeline -------
__global__ void k_attn(const float* __restrict__ We, int out_sel,
                       float* __restrict__ out, int n) {
    int w = (blockIdx.x * blockDim.x + threadIdx.x) >> 5;
    int lane = threadIdx.x & 31;
    if (w >= n) return;
    float* optr = (out_sel == 0) ? g_h1 : out;

    float we[EDIM][HEADS];
#pragma unroll
    for (int j = 0; j < EDIM; j++)
#pragma unroll
        for (int c = 0; c < HEADS; c++) we[j][c] = We[j * D + c * HID + lane];

    float q[HEADS];
#pragma unroll
    for (int c = 0; c < HEADS; c++) q[c] = g_Q[w * D + c * HID + lane];

    float m[HEADS], s[HEADS], acc[HEADS];
#pragma unroll
    for (int c = 0; c < HEADS; c++) { m[c] = -1e30f; s[c] = 0.0f; acc[c] = 0.0f; }

    int beg = g_rowptr[w];
    int end = g_rowptr[w + 1];
    const float sc = 0.17677669529663687f;  // 1/sqrt(32)

    float4 ea;
    float k0, k1, k2, v0, v1, v2;
    if (beg < end) {
        int sidx = g_psrc[beg];
        ea = g_pea[beg];
        int kb = sidx * D;
        k0 = g_K[kb + lane];            k1 = g_K[kb + HID + lane];
        k2 = g_K[kb + 2 * HID + lane];
        v0 = g_V[kb + lane];            v1 = g_V[kb + HID + lane];
        v2 = g_V[kb + 2 * HID + lane];
    }

    for (int i = beg; i < end; i++) {
        float4 nea;
        float nk0, nk1, nk2, nv0, nv1, nv2;
        if (i + 1 < end) {
            int nsidx = g_psrc[i + 1];
            nea = g_pea[i + 1];
            int nb = nsidx * D;
            nk0 = g_K[nb + lane];            nk1 = g_K[nb + HID + lane];
            nk2 = g_K[nb + 2 * HID + lane];
            nv0 = g_V[nb + lane];            nv1 = g_V[nb + HID + lane];
            nv2 = g_V[nb + 2 * HID + lane];
        }

        float eev[HEADS];
#pragma unroll
        for (int c = 0; c < HEADS; c++)
            eev[c] = ea.x * we[0][c] + ea.y * we[1][c] + ea.z * we[2][c] + ea.w * we[3][c];
        float p0 = q[0] * (k0 + eev[0]);
        float p1 = q[1] * (k1 + eev[1]);
        float p2 = q[2] * (k2 + eev[2]);
#pragma unroll
        for (int off = 16; off > 0; off >>= 1) {
            p0 += __shfl_xor_sync(0xFFFFFFFFu, p0, off);
            p1 += __shfl_xor_sync(0xFFFFFFFFu, p1, off);
            p2 += __shfl_xor_sync(0xFFFFFFFFu, p2, off);
        }
        float l[HEADS] = {p0 * sc, p1 * sc, p2 * sc};
        float vv[HEADS] = {v0 + eev[0], v1 + eev[1], v2 + eev[2]};
#pragma unroll
        for (int c = 0; c < HEADS; c++) {
            float nm = fmaxf(m[c], l[c]);
            float corr = __expf(m[c] - nm);
            float p = __expf(l[c] - nm);
            s[c] = s[c] * corr + p;
            m[c] = nm;
            acc[c] = acc[c] * corr + p * vv[c];
        }

        if (i + 1 < end) {
            ea = nea;
            k0 = nk0; k1 = nk1; k2 = nk2;
            v0 = nv0; v1 = nv1; v2 = nv2;
        }
    }
#pragma unroll
    for (int c = 0; c < HEADS; c++) {
        float o = acc[c] / (s[c] + 1e-16f) + g_S[w * D + c * HID + lane];
        optr[w * D + c * HID + lane] = tanhf(o);
    }
}

// ---------------- launch ----------------
extern "C" void kernel_launch(void* const* d_in, const int* in_sizes, int n_in,
                              void* d_out, int out_size) {
    const float* x     = (const float*)d_in[0];
    const int*   eidx  = (const int*)d_in[1];
    const float* eattr = (const float*)d_in[2];
    const float* W1    = (const float*)d_in[3];
    const float* b1    = (const float*)d_in[4];
    const float* Wq1 = (const float*)d_in[5];  const float* bq1 = (const float*)d_in[6];
    const float* Wk1 = (const float*)d_in[7];  const float* bk1 = (const float*)d_in[8];
    const float* Wv1 = (const float*)d_in[9];  const float* bv1 = (const float*)d_in[10];
    const float* We1 = (const float*)d_in[11];
    const float* Ws1 = (const float*)d_in[12]; const float* bs1 = (const float*)d_in[13];
    const float* Wq2 = (const float*)d_in[14]; const float* bq2 = (const float*)d_in[15];
    const float* Wk2 = (const float*)d_in[16]; const float* bk2 = (const float*)d_in[17];
    const float* Wv2 = (const float*)d_in[18]; const float* bv2 = (const float*)d_in[19];
    const float* We2 = (const float*)d_in[20];
    const float* Ws2 = (const float*)d_in[21]; const float* bs2 = (const float*)d_in[22];

    int N = in_sizes[0] / FIN;
    int E = in_sizes[2] / EDIM;
    const int* src = eidx;
    const int* dst = eidx + E;
    float* out = (float*)d_out;

    int eb = (E + 255) / 256;              // 3125
    int pb = (N + 15) / 16;                // 3125 proj blocks

    // 0: layer-0 MLP + histogram + lb-state zero
    k_l0_hist<<<eb, 256>>>(x, W1, b1, dst, N, E);
    // 1: scan (also restores g_cnt to zero)
    k_scan_lb<<<(N + 1023) / 1024, 256>>>(N, E);
    // 2: fused scatter + layer-1 projection
    k_scatter_proj1<<<eb + pb, 256>>>(src, dst, (const float4*)eattr, E, eb,
                                      Wq1, bq1, Wk1, bk1, Wv1, bv1, Ws1, bs1, N);
    // 3: attention layer 1  (ncu capture slot)
    k_attn<<<(N * 32 + 255) / 256, 256>>>(We1, 0, out, N);
    // 4: layer-2 projection
    k_proj2<<<pb, 256>>>(Wq2, bq2, Wk2, bk2, Wv2, bv2, Ws2, bs2, N);
    // 5: attention layer 2
    k_attn<<<(N * 32 + 255) / 256, 256>>>(We2, 1, out, N);
}

// round 7
// speedup vs baseline: 1.0870x; 1.0870x over previous
#include <cuda_runtime.h>
#include <math.h>

#define NN 50000
#define EE 800000
#define D 96
#define HID 32
#define HEADS 3
#define FIN 16
#define F0 8
#define EDIM 4
// (1/sqrt(32)) * log2(e): fold softmax scale + exp->exp2 into Q at projection time
#define SC2L 0.25504070896656615f

// ---- scratch (static device globals; zero-initialized at module load) ----
__device__ float g_h0[NN * F0];
__device__ float g_h1[NN * D];
__device__ float g_Q[NN * D];            // pre-scaled by SC2L
__device__ float g_KV[NN * 2 * D];       // per-node interleaved: K[96] then V[96] (768B records)
__device__ float g_S[NN * D];
__device__ int   g_cnt[NN];              // zero at entry of every launch (self-restoring)
__device__ int   g_rowptr[NN + 1];
__device__ int   g_cur[NN];
__device__ int   g_psrc[EE];             // src index in CSR-permuted order
__device__ float4 g_pea[EE];             // edge_attr in CSR-permuted order
__device__ volatile int g_lb_status[64];
__device__ volatile int g_lb_agg[64];
__device__ volatile int g_lb_pref[64];

// ------- launch 0: layer-0 MLP + dst histogram + lookback-state zeroing -------
__global__ void k_l0_hist(const float* __restrict__ x, const float* __restrict__ W1,
                          const float* __restrict__ b1, const int* __restrict__ dst,
                          int n, int e) {
    int i = blockIdx.x * blockDim.x + threadIdx.x;
    if (i < 64) g_lb_status[i] = 0;
    if (i < e) atomicAdd(&g_cnt[dst[i]], 1);
    if (i >= n) return;
    float xr[FIN];
    const float4* xv = reinterpret_cast<const float4*>(x + i * FIN);
#pragma unroll
    for (int j = 0; j < 4; j++) {
        float4 t = xv[j];
        xr[j * 4 + 0] = t.x; xr[j * 4 + 1] = t.y; xr[j * 4 + 2] = t.z; xr[j * 4 + 3] = t.w;
    }
#pragma unroll
    for (int o = 0; o < F0; o++) {
        float acc = b1[o];
#pragma unroll
        for (int k = 0; k < FIN; k++) acc += xr[k] * W1[k * F0 + o];
        g_h0[i * F0 + o] = tanhf(acc);
    }
}

// ------- launch 1: single-pass scan (decoupled lookback); zeroes g_cnt after use -------
__global__ void k_scan_lb(int n, int etot) {
    __shared__ int sh[256];
    __shared__ int sh_off;
    int b = blockIdx.x, t = threadIdx.x;
    int base = (b * 256 + t) * 4;
    int c[4];
    int local = 0;
#pragma unroll
    for (int j = 0; j < 4; j++) {
        int i = base + j;
        c[j] = (i < n) ? g_cnt[i] : 0;
        if (i < n) g_cnt[i] = 0;
        local += c[j];
    }
    sh[t] = local;
    __syncthreads();
    for (int off = 1; off < 256; off <<= 1) {
        int u = (t >= off) ? sh[t - off] : 0;
        __syncthreads();
        sh[t] += u;
        __syncthreads();
    }
    int incl = sh[t];
    int agg = sh[255];
    if (t == 255) {
        g_lb_agg[b] = agg;
        __threadfence();
        g_lb_status[b] = (b == 0) ? 0 : 1;
    }
    __syncthreads();
    if (t == 0) {
        int excl = 0;
        for (int p = b - 1; p >= 0; --p) {
            int st;
            do { st = g_lb_status[p]; } while (st == 0);
            if (st == 2) { excl += g_lb_pref[p]; break; }
            excl += g_lb_agg[p];
        }
        sh_off = excl;
        g_lb_pref[b] = excl + agg;
        __threadfence();
        g_lb_status[b] = 2;
        if (b == 0) g_rowptr[n] = etot;
    }
    __syncthreads();
    int run = sh_off + incl - local;
#pragma unroll
    for (int j = 0; j < 4; j++) {
        int i = base + j;
        if (i < n) {
            g_rowptr[i] = run;
            g_cur[i] = run;
            run += c[j];
        }
    }
}

// ------- proj body: Q (pre-scaled), KV interleaved, S -------
template <int FI>
__device__ __forceinline__ void proj_body(
        const float* __restrict__ in, int node0,
        const float* __restrict__ Wq, const float* __restrict__ bq,
        const float* __restrict__ Wk, const float* __restrict__ bk,
        const float* __restrict__ Wv, const float* __restrict__ bv,
        const float* __restrict__ Ws, const float* __restrict__ bs,
        int n, float* shp) {
    const int NB = 16, NG = 8;
    float (*sh)[FI] = (float (*)[FI])shp;
    int t = threadIdx.x;
    for (int idx = t; idx < NB * FI; idx += 256) {
        int j = idx / FI, k = idx % FI;
        int nd = node0 + j;
        sh[j][k] = (nd < n) ? in[nd * FI + k] : 0.0f;
    }
    __syncthreads();
    int grp = t / D;
    int d = t - grp * D;
    if (grp < 2) {
        int j0 = grp * NG;
        float aq[NG], ak[NG], av[NG], as_[NG];
        float vbq = bq[d], vbk = bk[d], vbv = bv[d], vbs = bs[d];
#pragma unroll
        for (int j = 0; j < NG; j++) { aq[j] = vbq; ak[j] = vbk; av[j] = vbv; as_[j] = vbs; }
        for (int k = 0; k < FI; k++) {
            float wq = Wq[k * D + d], wk = Wk[k * D + d], wv = Wv[k * D + d], ws = Ws[k * D + d];
#pragma unroll
            for (int j = 0; j < NG; j++) {
                float h = sh[j0 + j][k];
                aq[j] += h * wq; ak[j] += h * wk; av[j] += h * wv; as_[j] += h * ws;
            }
        }
#pragma unroll
        for (int j = 0; j < NG; j++) {
            int nd = node0 + j0 + j;
            if (nd < n) {
                g_Q[nd * D + d] = aq[j] * SC2L;
                g_KV[nd * 2 * D + d] = ak[j];
                g_KV[nd * 2 * D + D + d] = av[j];
                g_S[nd * D + d] = as_[j];
            }
        }
    }
}

// ------- launch 2: fused scatter + layer-1 projection -------
__global__ void k_scatter_proj1(const int* __restrict__ src, const int* __restrict__ dst,
                                const float4* __restrict__ ea, int e, int scat_blocks,
                                const float* __restrict__ Wq, const float* __restrict__ bq,
                                const float* __restrict__ Wk, const float* __restrict__ bk,
                                const float* __restrict__ Wv, const float* __restrict__ bv,
                                const float* __restrict__ Ws, const float* __restrict__ bs,
                                int n) {
    __shared__ float shp[16 * F0];
    if ((int)blockIdx.x < scat_blocks) {
        int i = blockIdx.x * 256 + threadIdx.x;
        if (i < e) {
            int d = dst[i];
            int pos = atomicAdd(&g_cur[d], 1);
            g_psrc[pos] = src[i];
            g_pea[pos] = ea[i];
        }
    } else {
        int node0 = (blockIdx.x - scat_blocks) * 16;
        proj_body<F0>(g_h0, node0, Wq, bq, Wk, bk, Wv, bv, Ws, bs, n, shp);
    }
}

// ------- launch 4: layer-2 projection -------
__global__ void k_proj2(const float* __restrict__ Wq, const float* __restrict__ bq,
                        const float* __restrict__ Wk, const float* __restrict__ bk,
                        const float* __restrict__ Wv, const float* __restrict__ bv,
                        const float* __restrict__ Ws, const float* __restrict__ bs,
                        int n) {
    __shared__ float shp[16 * D];
    int node0 = blockIdx.x * 16;
    proj_body<D>(g_h1, node0, Wq, bq, Wk, bk, Wv, bv, Ws, bs, n, shp);
}

__device__ __forceinline__ float dot4(float4 a, float4 b) {
    return a.x * b.x + a.y * b.y + a.z * b.z + a.w * b.w;
}

// ------- attention: 4 lanes/edge, 8 dst nodes/warp, unnormalized exp2 softmax -------
// lane = g*4 + j; group g handles node warp*8+g; sublane j handles float4 slots {4f+j}.
// Slot f's head = f>>1. Per-edge ee eliminated algebraically via t = q.We (logit) and
// r = sum(p*ea) (value, folded with We at epilogue).
__global__ void __launch_bounds__(256) k_attn(const float* __restrict__ We, int out_sel,
                                              float* __restrict__ out, int n, int e) {
    int warp = (blockIdx.x * blockDim.x + threadIdx.x) >> 5;
    int lane = threadIdx.x & 31;
    int j = lane & 3;
    int node = warp * 8 + (lane >> 2);
    bool nvalid = node < n;
    int nd = nvalid ? node : 0;
    float* optr = (out_sel == 0) ? g_h1 : out;

    const float4* Q4 = (const float4*)g_Q;
    const float4* KV4 = (const float4*)g_KV;
    const float4* S4 = (const float4*)g_S;
    const float4* We4 = (const float4*)We;
    float4* O4 = (float4*)optr;

    // q (pre-scaled by SC2L in projection)
    float4 q4[6];
#pragma unroll
    for (int f = 0; f < 6; f++) q4[f] = Q4[nd * 24 + 4 * f + j];

    // t[c][jj] = q . We[jj] restricted to head c (reduced over the 4 sublanes)
    float t[HEADS][EDIM];
#pragma unroll
    for (int c = 0; c < HEADS; c++)
#pragma unroll
        for (int jj = 0; jj < EDIM; jj++) {
            float4 wa = We4[jj * 24 + 4 * (2 * c) + j];
            float4 wb = We4[jj * 24 + 4 * (2 * c + 1) + j];
            float p = dot4(q4[2 * c], wa) + dot4(q4[2 * c + 1], wb);
            p += __shfl_xor_sync(0xFFFFFFFFu, p, 1);
            p += __shfl_xor_sync(0xFFFFFFFFu, p, 2);
            t[c][jj] = p;
        }

    int beg = nvalid ? g_rowptr[node] : 0;
    int end = nvalid ? g_rowptr[node + 1] : 0;
    int cnt = end - beg;
    int itmax = cnt;
    itmax = max(itmax, __shfl_xor_sync(0xFFFFFFFFu, itmax, 4));
    itmax = max(itmax, __shfl_xor_sync(0xFFFFFFFFu, itmax, 8));
    itmax = max(itmax, __shfl_xor_sync(0xFFFFFFFFu, itmax, 16));

    float4 acc4[6];
#pragma unroll
    for (int f = 0; f < 6; f++) acc4[f] = make_float4(0.f, 0.f, 0.f, 0.f);
    float s0 = 0.f, s1 = 0.f, s2 = 0.f;
    float r[HEADS][EDIM];
#pragma unroll
    for (int c = 0; c < HEADS; c++)
#pragma unroll
        for (int jj = 0; jj < EDIM; jj++) r[c][jj] = 0.f;

    for (int it = 0; it < itmax; it++) {
        bool v = it < cnt;
        int i = min(beg + it, e - 1);
        int sidx = g_psrc[i];
        float4 ea = g_pea[i];
        int base = sidx * 48;  // 192 floats = 48 float4 per node record
        float4 kk[6], vv[6];
#pragma unroll
        for (int f = 0; f < 6; f++) kk[f] = KV4[base + 4 * f + j];
#pragma unroll
        for (int f = 0; f < 6; f++) vv[f] = KV4[base + 24 + 4 * f + j];

        float p0 = dot4(q4[0], kk[0]) + dot4(q4[1], kk[1]);
        float p1 = dot4(q4[2], kk[2]) + dot4(q4[3], kk[3]);
        float p2 = dot4(q4[4], kk[4]) + dot4(q4[5], kk[5]);
        p0 += __shfl_xor_sync(0xFFFFFFFFu, p0, 1);
        p0 += __shfl_xor_sync(0xFFFFFFFFu, p0, 2);
        p1 += __shfl_xor_sync(0xFFFFFFFFu, p1, 1);
        p1 += __shfl_xor_sync(0xFFFFFFFFu, p1, 2);
        p2 += __shfl_xor_sync(0xFFFFFFFFu, p2, 1);
        p2 += __shfl_xor_sync(0xFFFFFFFFu, p2, 2);

        float l0 = p0 + ea.x * t[0][0] + ea.y * t[0][1] + ea.z * t[0][2] + ea.w * t[0][3];
        float l1 = p1 + ea.x * t[1][0] + ea.y * t[1][1] + ea.z * t[1][2] + ea.w * t[1][3];
        float l2 = p2 + ea.x * t[2][0] + ea.y * t[2][1] + ea.z * t[2][2] + ea.w * t[2][3];
        float e0 = v ? exp2f(l0) : 0.f;
        float e1 = v ? exp2f(l1) : 0.f;
        float e2 = v ? exp2f(l2) : 0.f;
        s0 += e0; s1 += e1; s2 += e2;
        r[0][0] += e0 * ea.x; r[0][1] += e0 * ea.y; r[0][2] += e0 * ea.z; r[0][3] += e0 * ea.w;
        r[1][0] += e1 * ea.x; r[1][1] += e1 * ea.y; r[1][2] += e1 * ea.z; r[1][3] += e1 * ea.w;
        r[2][0] += e2 * ea.x; r[2][1] += e2 * ea.y; r[2][2] += e2 * ea.z; r[2][3] += e2 * ea.w;
#pragma unroll
        for (int f = 0; f < 6; f++) {
            float pc = (f < 2) ? e0 : (f < 4) ? e1 : e2;
            acc4[f].x += pc * vv[f].x;
            acc4[f].y += pc * vv[f].y;
            acc4[f].z += pc * vv[f].z;
            acc4[f].w += pc * vv[f].w;
        }
    }

    if (!nvalid) return;
    float inv[HEADS];
    inv[0] = 1.0f / (s0 + 1e-16f);
    inv[1] = 1.0f / (s1 + 1e-16f);
    inv[2] = 1.0f / (s2 + 1e-16f);
#pragma unroll
    for (int f = 0; f < 6; f++) {
        int c = f >> 1;
        int G = 4 * f + j;
        float4 w0 = We4[0 * 24 + G];
        float4 w1 = We4[1 * 24 + G];
        float4 w2 = We4[2 * 24 + G];
        float4 w3 = We4[3 * 24 + G];
        float4 sk = S4[node * 24 + G];
        float4 o;
        o.x = (acc4[f].x + r[c][0] * w0.x + r[c][1] * w1.x + r[c][2] * w2.x + r[c][3] * w3.x) * inv[c] + sk.x;
        o.y = (acc4[f].y + r[c][0] * w0.y + r[c][1] * w1.y + r[c][2] * w2.y + r[c][3] * w3.y) * inv[c] + sk.y;
        o.z = (acc4[f].z + r[c][0] * w0.z + r[c][1] * w1.z + r[c][2] * w2.z + r[c][3] * w3.z) * inv[c] + sk.z;
        o.w = (acc4[f].w + r[c][0] * w0.w + r[c][1] * w1.w + r[c][2] * w2.w + r[c][3] * w3.w) * inv[c] + sk.w;
        o.x = tanhf(o.x); o.y = tanhf(o.y); o.z = tanhf(o.z); o.w = tanhf(o.w);
        O4[node * 24 + G] = o;
    }
}

// ---------------- launch ----------------
extern "C" void kernel_launch(void* const* d_in, const int* in_sizes, int n_in,
                              void* d_out, int out_size) {
    const float* x     = (const float*)d_in[0];
    const int*   eidx  = (const int*)d_in[1];
    const float* eattr = (const float*)d_in[2];
    const float* W1    = (const float*)d_in[3];
    const float* b1    = (const float*)d_in[4];
    const float* Wq1 = (const float*)d_in[5];  const float* bq1 = (const float*)d_in[6];
    const float* Wk1 = (const float*)d_in[7];  const float* bk1 = (const float*)d_in[8];
    const float* Wv1 = (const float*)d_in[9];  const float* bv1 = (const float*)d_in[10];
    const float* We1 = (const float*)d_in[11];
    const float* Ws1 = (const float*)d_in[12]; const float* bs1 = (const float*)d_in[13];
    const float* Wq2 = (const float*)d_in[14]; const float* bq2 = (const float*)d_in[15];
    const float* Wk2 = (const float*)d_in[16]; const float* bk2 = (const float*)d_in[17];
    const float* Wv2 = (const float*)d_in[18]; const float* bv2 = (const float*)d_in[19];
    const float* We2 = (const float*)d_in[20];
    const float* Ws2 = (const float*)d_in[21]; const float* bs2 = (const float*)d_in[22];

    int N = in_sizes[0] / FIN;
    int E = in_sizes[2] / EDIM;
    const int* src = eidx;
    const int* dst = eidx + E;
    float* out = (float*)d_out;

    int eb = (E + 255) / 256;
    int pb = (N + 15) / 16;
    int ab = (N + 63) / 64;   // attn: 8 warps/block * 8 nodes/warp

    // 0: layer-0 MLP + histogram + lb-state zero
    k_l0_hist<<<eb, 256>>>(x, W1, b1, dst, N, E);
    // 1: scan (restores g_cnt to zero)
    k_scan_lb<<<(N + 1023) / 1024, 256>>>(N, E);
    // 2: fused scatter + layer-1 projection
    k_scatter_proj1<<<eb + pb, 256>>>(src, dst, (const float4*)eattr, E, eb,
                                      Wq1, bq1, Wk1, bk1, Wv1, bv1, Ws1, bs1, N);
    // 3: attention layer 1  (ncu capture slot)
    k_attn<<<ab, 256>>>(We1, 0, out, N, E);
    // 4: layer-2 projection
    k_proj2<<<pb, 256>>>(Wq2, bq2, Wk2, bk2, Wv2, bv2, Ws2, bs2, N);
    // 5: attention layer 2
    k_attn<<<ab, 256>>>(We2, 1, out, N, E);
}